// round 4
// baseline (speedup 1.0000x reference)
#include <cuda_runtime.h>
#include <cuda_bf16.h>

// ---------------------------------------------------------------------------
// Problem constants
// ---------------------------------------------------------------------------
constexpr int B   = 2;
constexpr int S   = 2048;
constexpr int H   = 2048;      // hidden
constexpr int NH  = 16;        // heads
constexpr int D   = 128;       // head dim
constexpr int M   = B * S;     // 4096 tokens
constexpr int H3  = 3 * H;     // 6144
constexpr float SM_SCALE = 0.08838834764831845f;  // 1/sqrt(128)

// ---------------------------------------------------------------------------
// Scratch (device globals; allocation-free per harness rules)
// ---------------------------------------------------------------------------
__device__ float g_qkv[(size_t)M * H3];     // [4096, 6144]  ~100 MB
__device__ float g_ctx[(size_t)M * H];      // [4096, 2048]  ~34 MB

// ---------------------------------------------------------------------------
// SIMT fp32 GEMM: C[128,128] tile = A[128,K] @ B[K,N] (+ bias[col])
// 256 threads, each owns an 8x8 micro-tile. K staged in 16-deep smem slices.
//   As[k][m] (A transposed on store), Bs[k][n] -> both inner-loop reads are
//   contiguous float4.
// ---------------------------------------------------------------------------
__global__ void gemm_simt_kernel(const float* __restrict__ A,  int lda,
                                 const float* __restrict__ Bm, int ldb,
                                 float* __restrict__ C,        int ldc,
                                 int K, const float* __restrict__ bias)
{
    __shared__ __align__(16) float As[16][132];   // [k][m]
    __shared__ __align__(16) float Bs[16][132];   // [k][n]

    const int tid = threadIdx.x;
    const int tm  = (tid >> 4) * 8;    // 16 row-groups
    const int tn  = (tid & 15) * 8;    // 16 col-groups
    const int m0  = blockIdx.y * 128;
    const int n0  = blockIdx.x * 128;

    A  += (size_t)m0 * lda;
    Bm += n0;
    C  += (size_t)m0 * ldc + n0;

    float acc[8][8];
#pragma unroll
    for (int i = 0; i < 8; i++)
#pragma unroll
        for (int j = 0; j < 8; j++) acc[i][j] = 0.0f;

    for (int k0 = 0; k0 < K; k0 += 16) {
        // stage A tile [128 m x 16 k], transposed into As[k][m]
#pragma unroll
        for (int i = tid; i < 512; i += 256) {
            int r = i >> 2, cb = (i & 3) * 4;
            float4 v = *reinterpret_cast<const float4*>(A + (size_t)r * lda + k0 + cb);
            As[cb + 0][r] = v.x; As[cb + 1][r] = v.y;
            As[cb + 2][r] = v.z; As[cb + 3][r] = v.w;
        }
        // stage B tile [16 k x 128 n]
#pragma unroll
        for (int i = tid; i < 512; i += 256) {
            int r = i >> 5, cb = (i & 31) * 4;
            *reinterpret_cast<float4*>(&Bs[r][cb]) =
                *reinterpret_cast<const float4*>(Bm + (size_t)(k0 + r) * ldb + cb);
        }
        __syncthreads();

#pragma unroll
        for (int kk = 0; kk < 16; kk++) {
            float a[8], b[8];
            *reinterpret_cast<float4*>(a)     = *reinterpret_cast<float4*>(&As[kk][tm]);
            *reinterpret_cast<float4*>(a + 4) = *reinterpret_cast<float4*>(&As[kk][tm + 4]);
            *reinterpret_cast<float4*>(b)     = *reinterpret_cast<float4*>(&Bs[kk][tn]);
            *reinterpret_cast<float4*>(b + 4) = *reinterpret_cast<float4*>(&Bs[kk][tn + 4]);
#pragma unroll
            for (int i = 0; i < 8; i++)
#pragma unroll
                for (int j = 0; j < 8; j++)
                    acc[i][j] = fmaf(a[i], b[j], acc[i][j]);
        }
        __syncthreads();
    }

    // epilogue
    float bv[8];
#pragma unroll
    for (int j = 0; j < 8; j++) bv[j] = bias ? bias[n0 + tn + j] : 0.0f;
#pragma unroll
    for (int i = 0; i < 8; i++) {
        float4 o0, o1;
        o0.x = acc[i][0] + bv[0]; o0.y = acc[i][1] + bv[1];
        o0.z = acc[i][2] + bv[2]; o0.w = acc[i][3] + bv[3];
        o1.x = acc[i][4] + bv[4]; o1.y = acc[i][5] + bv[5];
        o1.z = acc[i][6] + bv[6]; o1.w = acc[i][7] + bv[7];
        *reinterpret_cast<float4*>(C + (size_t)(tm + i) * ldc + tn)     = o0;
        *reinterpret_cast<float4*>(C + (size_t)(tm + i) * ldc + tn + 4) = o1;
    }
}

// ---------------------------------------------------------------------------
// Fused flash-style attention, SIMT fp32.
// Per block: one (bh, 128-query) tile. Streaming softmax WITHOUT running max
// (scores are O(+-10) in fp32 -> exp cannot overflow; mask<=0 only underflows).
//   For each 128-key tile: S = Q K^T (registers) -> P = exp(S*scale+mask),
//   P stored transposed to smem, rowSum accumulated; O_reg += P @ V.
// Final: O / rowSum.
// grid (16, 32), 256 threads, ~203 KB dynamic smem.
// ---------------------------------------------------------------------------
constexpr int LDS = 132;
constexpr int FLASH_SMEM_FLOATS = 3 * 128 * LDS + 128;
constexpr int FLASH_SMEM_BYTES  = FLASH_SMEM_FLOATS * 4;

__global__ void flash_attn_simt_kernel(const float* __restrict__ mask)
{
    extern __shared__ __align__(16) float smem[];
    float* sQt    = smem;                 // [128 d][132]  Q transposed: sQt[d][q]
    float* sKV    = smem + 128 * LDS;     // K transposed sKt[d][k]; later V[k][d]
    float* sPt    = smem + 2 * 128 * LDS; // P transposed: sPt[k][q]
    float* rowSum = smem + 3 * 128 * LDS; // [128]

    const int tid = threadIdx.x;
    const int tm  = (tid >> 4) * 8;       // query rows owned
    const int tn  = (tid & 15) * 8;       // key cols / head-dim cols owned

    const int z  = blockIdx.y;            // bh
    const int b  = z >> 4;
    const int h  = z & 15;
    const int q0 = blockIdx.x * 128;

    const float* __restrict__ Qg = g_qkv + (size_t)(b * S + q0) * H3 + h * D;
    const float* __restrict__ maskb = mask + (size_t)b * S;

    // ---- load Q tile [128 q x 128 d], transposed into sQt[d][q] ----
#pragma unroll
    for (int i = tid; i < 4096; i += 256) {
        int r = i >> 5, cb = (i & 31) * 4;
        float4 v = *reinterpret_cast<const float4*>(Qg + (size_t)r * H3 + cb);
        sQt[(cb + 0) * LDS + r] = v.x; sQt[(cb + 1) * LDS + r] = v.y;
        sQt[(cb + 2) * LDS + r] = v.z; sQt[(cb + 3) * LDS + r] = v.w;
    }
    if (tid < 128) rowSum[tid] = 0.0f;

    float racc[8][8];                      // persistent O accumulator
#pragma unroll
    for (int i = 0; i < 8; i++)
#pragma unroll
        for (int j = 0; j < 8; j++) racc[i][j] = 0.0f;

    for (int jt = 0; jt < S / 128; jt++) {
        const int n0 = jt * 128;
        const float* __restrict__ Kg = g_qkv + (size_t)(b * S + n0) * H3 + H     + h * D;
        const float* __restrict__ Vg = g_qkv + (size_t)(b * S + n0) * H3 + 2 * H + h * D;

        // ---- load K tile [128 k x 128 d] transposed into sKt[d][k] ----
#pragma unroll
        for (int i = tid; i < 4096; i += 256) {
            int r = i >> 5, cb = (i & 31) * 4;
            float4 v = *reinterpret_cast<const float4*>(Kg + (size_t)r * H3 + cb);
            sKV[(cb + 0) * LDS + r] = v.x; sKV[(cb + 1) * LDS + r] = v.y;
            sKV[(cb + 2) * LDS + r] = v.z; sKV[(cb + 3) * LDS + r] = v.w;
        }
        __syncthreads();

        // ---- S = Q K^T in registers: s[i][j] over (tm+i, tn+j) ----
        float sacc[8][8];
#pragma unroll
        for (int i = 0; i < 8; i++)
#pragma unroll
            for (int j = 0; j < 8; j++) sacc[i][j] = 0.0f;

#pragma unroll 4
        for (int dd = 0; dd < 128; dd++) {
            float a[8], bb[8];
            *reinterpret_cast<float4*>(a)      = *reinterpret_cast<float4*>(&sQt[dd * LDS + tm]);
            *reinterpret_cast<float4*>(a + 4)  = *reinterpret_cast<float4*>(&sQt[dd * LDS + tm + 4]);
            *reinterpret_cast<float4*>(bb)     = *reinterpret_cast<float4*>(&sKV[dd * LDS + tn]);
            *reinterpret_cast<float4*>(bb + 4) = *reinterpret_cast<float4*>(&sKV[dd * LDS + tn + 4]);
#pragma unroll
            for (int i = 0; i < 8; i++)
#pragma unroll
                for (int j = 0; j < 8; j++)
                    sacc[i][j] = fmaf(a[i], bb[j], sacc[i][j]);
        }
        __syncthreads();   // all warps done reading sKV (S phase complete)

        // ---- P = exp(S*scale + mask); store transposed; row partial sums ----
        float mv[8];
#pragma unroll
        for (int j = 0; j < 8; j++) mv[j] = maskb[n0 + tn + j];

        float rowpart[8];
#pragma unroll
        for (int i = 0; i < 8; i++) rowpart[i] = 0.0f;

#pragma unroll
        for (int i = 0; i < 8; i++) {
#pragma unroll
            for (int j = 0; j < 8; j++) {
                float p = __expf(fmaf(sacc[i][j], SM_SCALE, mv[j]));
                rowpart[i] += p;
                sPt[(tn + j) * LDS + tm + i] = p;
            }
        }
        // reduce rowpart across the 16 threads sharing rows (lanes (tid&15))
#pragma unroll
        for (int i = 0; i < 8; i++) {
#pragma unroll
            for (int off = 1; off < 16; off <<= 1)
                rowpart[i] += __shfl_xor_sync(0xffffffffu, rowpart[i], off, 16);
        }
        if ((tid & 15) == 0) {
#pragma unroll
            for (int i = 0; i < 8; i++) rowSum[tm + i] += rowpart[i];
        }

        // ---- load V tile [128 k x 128 d] natural layout into sKV[k][d] ----
#pragma unroll
        for (int i = tid; i < 4096; i += 256) {
            int r = i >> 5, cb = (i & 31) * 4;
            *reinterpret_cast<float4*>(&sKV[r * LDS + cb]) =
                *reinterpret_cast<const float4*>(Vg + (size_t)r * H3 + cb);
        }
        __syncthreads();   // sPt + V visible to all

        // ---- O += P @ V : racc[i][j] over (q=tm+i, d=tn+j) ----
#pragma unroll 4
        for (int kk = 0; kk < 128; kk++) {
            float a[8], bb[8];
            *reinterpret_cast<float4*>(a)      = *reinterpret_cast<float4*>(&sPt[kk * LDS + tm]);
            *reinterpret_cast<float4*>(a + 4)  = *reinterpret_cast<float4*>(&sPt[kk * LDS + tm + 4]);
            *reinterpret_cast<float4*>(bb)     = *reinterpret_cast<float4*>(&sKV[kk * LDS + tn]);
            *reinterpret_cast<float4*>(bb + 4) = *reinterpret_cast<float4*>(&sKV[kk * LDS + tn + 4]);
#pragma unroll
            for (int i = 0; i < 8; i++)
#pragma unroll
                for (int j = 0; j < 8; j++)
                    racc[i][j] = fmaf(a[i], bb[j], racc[i][j]);
        }
        __syncthreads();   // before next tile overwrites sKV / sPt
    }

    // ---- epilogue: normalize and store ctx ----
#pragma unroll
    for (int i = 0; i < 8; i++) {
        const float inv = 1.0f / rowSum[tm + i];
        float* dst = g_ctx + (size_t)(b * S + q0 + tm + i) * H + h * D + tn;
        float4 o0, o1;
        o0.x = racc[i][0] * inv; o0.y = racc[i][1] * inv;
        o0.z = racc[i][2] * inv; o0.w = racc[i][3] * inv;
        o1.x = racc[i][4] * inv; o1.y = racc[i][5] * inv;
        o1.z = racc[i][6] * inv; o1.w = racc[i][7] * inv;
        *reinterpret_cast<float4*>(dst)     = o0;
        *reinterpret_cast<float4*>(dst + 4) = o1;
    }
}

// ---------------------------------------------------------------------------
// Launch — inputs identified BY ELEMENT COUNT (robust to ordering).
// ---------------------------------------------------------------------------
extern "C" void kernel_launch(void* const* d_in, const int* in_sizes, int n_in,
                              void* d_out, int out_size)
{
    const float* hidden = nullptr;
    const float* mask   = nullptr;
    const float* W_qkv  = nullptr;
    const float* b_qkv  = nullptr;
    const float* W_out  = nullptr;
    const float* b_out  = nullptr;

    for (int i = 0; i < n_in; i++) {
        switch (in_sizes[i]) {
            case 8388608:  hidden = (const float*)d_in[i]; break;  // [2,2048,2048]
            case 4096:     mask   = (const float*)d_in[i]; break;  // [2,1,1,2048]
            case 12582912: W_qkv  = (const float*)d_in[i]; break;  // [2048,6144]
            case 6144:     b_qkv  = (const float*)d_in[i]; break;  // [6144]
            case 4194304:  W_out  = (const float*)d_in[i]; break;  // [2048,2048]
            case 2048:     b_out  = (const float*)d_in[i]; break;  // [2048]
            default: break;
        }
    }
    float* out = (float*)d_out;                    // [2,2048,2048]

    cudaFuncSetAttribute(flash_attn_simt_kernel,
                         cudaFuncAttributeMaxDynamicSharedMemorySize,
                         FLASH_SMEM_BYTES);

    // QKV = hidden @ W_qkv + b_qkv
    float* qkv_ptr;  cudaGetSymbolAddress((void**)&qkv_ptr, g_qkv);
    float* ctx_ptr;  cudaGetSymbolAddress((void**)&ctx_ptr, g_ctx);

    gemm_simt_kernel<<<dim3(H3 / 128, M / 128), 256>>>(
        hidden, H, W_qkv, H3, qkv_ptr, H3, H, b_qkv);

    flash_attn_simt_kernel<<<dim3(S / 128, B * NH), 256, FLASH_SMEM_BYTES>>>(mask);

    gemm_simt_kernel<<<dim3(H / 128, M / 128), 256>>>(
        ctx_ptr, H, W_out, H, out, H, H, b_out);
}

// round 5
// speedup vs baseline: 3.0510x; 3.0510x over previous
#include <cuda_runtime.h>
#include <cstdint>

// ---------------------------------------------------------------------------
// Problem constants
// ---------------------------------------------------------------------------
constexpr int B   = 2;
constexpr int S   = 2048;
constexpr int H   = 2048;
constexpr int NH  = 16;
constexpr int D   = 128;
constexpr int M   = B * S;     // 4096
constexpr int H3  = 3 * H;     // 6144
constexpr float SM_SCALE = 0.08838834764831845f;  // 1/sqrt(128)

// ---------------------------------------------------------------------------
// Scratch
// ---------------------------------------------------------------------------
__device__ float g_qkv[(size_t)M * H3];     // [4096, 6144]
__device__ float g_ctx[(size_t)M * H];      // [4096, 2048]

// ---------------------------------------------------------------------------
// tf32 helpers.  cvt.rna.tf32.f32 returns the fp32 bit pattern with the low
// 13 mantissa bits zeroed — storable as float, reusable directly as the .b32
// mma operand via __float_as_uint.
// ---------------------------------------------------------------------------
__device__ __forceinline__ float f2tf(float x) {
    uint32_t r;
    asm("cvt.rna.tf32.f32 %0, %1;" : "=r"(r) : "f"(x));
    return __uint_as_float(r);
}

// mma.m16n8k8 tf32: D(16x8) = A(16x8) * B(8x8) + C
// A regs: a0=(g,t) a1=(g+8,t) a2=(g,t+4) a3=(g+8,t+4)   [row=m, col=k]
// B regs: b0=(t,g) b1=(t+4,g)                            [row=k, col=n]
// C regs: c0=(g,2t) c1=(g,2t+1) c2=(g+8,2t) c3=(g+8,2t+1)
__device__ __forceinline__ void mma8(float* d, const float* a, const float* b) {
    asm volatile(
        "mma.sync.aligned.m16n8k8.row.col.f32.tf32.tf32.f32 "
        "{%0,%1,%2,%3}, {%4,%5,%6,%7}, {%8,%9}, {%0,%1,%2,%3};\n"
        : "+f"(d[0]), "+f"(d[1]), "+f"(d[2]), "+f"(d[3])
        : "r"(__float_as_uint(a[0])), "r"(__float_as_uint(a[1])),
          "r"(__float_as_uint(a[2])), "r"(__float_as_uint(a[3])),
          "r"(__float_as_uint(b[0])), "r"(__float_as_uint(b[1])));
}

// ---------------------------------------------------------------------------
// GEMM: C[128,128/block] = A[M,K] @ B[K,N] + bias.  tf32 mma, k-step 32.
//   As[m][k] stride 36  (A-pattern reads: bank = 4g+t, conflict-free)
//   Bs[k][n] stride 136 (B-pattern reads: bank = 8t+g, conflict-free)
// ---------------------------------------------------------------------------
constexpr int AKP = 36;
constexpr int BNP = 136;

__global__ __launch_bounds__(256)
void gemm_mma_kernel(const float* __restrict__ A,  int lda,
                     const float* __restrict__ Bm, int ldb,
                     float* __restrict__ C,        int ldc,
                     int K, const float* __restrict__ bias)
{
    __shared__ __align__(16) float As[128 * AKP];
    __shared__ __align__(16) float Bs[32 * BNP];

    const int tid  = threadIdx.x;
    const int warp = tid >> 5, lane = tid & 31;
    const int g = lane >> 2, t = lane & 3;
    const int wm = (warp >> 2) * 64, wn = (warp & 3) * 32;
    const int m0 = blockIdx.y * 128, n0 = blockIdx.x * 128;

    A  += (size_t)m0 * lda;
    Bm += n0;
    C  += (size_t)m0 * ldc + n0;

    float acc[4][4][4];
#pragma unroll
    for (int mi = 0; mi < 4; mi++)
#pragma unroll
        for (int nj = 0; nj < 4; nj++)
#pragma unroll
            for (int r = 0; r < 4; r++) acc[mi][nj][r] = 0.0f;

    for (int k0 = 0; k0 < K; k0 += 32) {
        // stage A [128 x 32] with tf32 rounding
#pragma unroll
        for (int i = tid; i < 1024; i += 256) {
            int r = i >> 3, c = (i & 7) * 4;
            float4 v = *reinterpret_cast<const float4*>(A + (size_t)r * lda + k0 + c);
            v.x = f2tf(v.x); v.y = f2tf(v.y); v.z = f2tf(v.z); v.w = f2tf(v.w);
            *reinterpret_cast<float4*>(&As[r * AKP + c]) = v;
        }
        // stage B [32 x 128] with tf32 rounding
#pragma unroll
        for (int i = tid; i < 1024; i += 256) {
            int r = i >> 5, c = (i & 31) * 4;
            float4 v = *reinterpret_cast<const float4*>(Bm + (size_t)(k0 + r) * ldb + c);
            v.x = f2tf(v.x); v.y = f2tf(v.y); v.z = f2tf(v.z); v.w = f2tf(v.w);
            *reinterpret_cast<float4*>(&Bs[r * BNP + c]) = v;
        }
        __syncthreads();

#pragma unroll
        for (int kk = 0; kk < 32; kk += 8) {
            float af[4][4], bf[4][2];
#pragma unroll
            for (int mi = 0; mi < 4; mi++) {
                const float* base = &As[(wm + mi * 16 + g) * AKP + kk];
                af[mi][0] = base[t];
                af[mi][1] = base[8 * AKP + t];
                af[mi][2] = base[t + 4];
                af[mi][3] = base[8 * AKP + t + 4];
            }
#pragma unroll
            for (int nj = 0; nj < 4; nj++) {
                const int col = wn + nj * 8 + g;
                bf[nj][0] = Bs[(kk + t) * BNP + col];
                bf[nj][1] = Bs[(kk + t + 4) * BNP + col];
            }
#pragma unroll
            for (int mi = 0; mi < 4; mi++)
#pragma unroll
                for (int nj = 0; nj < 4; nj++)
                    mma8(acc[mi][nj], af[mi], bf[nj]);
        }
        __syncthreads();
    }

    // epilogue: c0,c1 contiguous (cols 2t,2t+1) -> float2 stores
#pragma unroll
    for (int mi = 0; mi < 4; mi++) {
#pragma unroll
        for (int nj = 0; nj < 4; nj++) {
            const int row = wm + mi * 16 + g;
            const int col = wn + nj * 8 + 2 * t;
            const float b0 = bias ? bias[n0 + col]     : 0.0f;
            const float b1 = bias ? bias[n0 + col + 1] : 0.0f;
            float2 lo = make_float2(acc[mi][nj][0] + b0, acc[mi][nj][1] + b1);
            float2 hi = make_float2(acc[mi][nj][2] + b0, acc[mi][nj][3] + b1);
            *reinterpret_cast<float2*>(C + (size_t)row * ldc + col)       = lo;
            *reinterpret_cast<float2*>(C + (size_t)(row + 8) * ldc + col) = hi;
        }
    }
}

// ---------------------------------------------------------------------------
// Fused flash attention with tf32 mma.
// Per block: (bh, 128 q). Streaming softmax without running max (scores are
// O(+-10) in fp32; mask<=0 can only underflow exp to 0).
// smem strides: Q 132 (A-pattern 4g+t), K 132 (B-pattern over keys: 4g+t),
//               V 136 (B-pattern over k-dim: 8t+g), P 132 (A-pattern).
// ---------------------------------------------------------------------------
constexpr int QP = 132, KSTR = 132, VSTR = 136, PP = 132;
constexpr int FLASH_SMEM_FLOATS = 128 * QP + 128 * VSTR + 128 * PP + 128 + S;
constexpr int FLASH_SMEM_BYTES  = FLASH_SMEM_FLOATS * 4;   // ~213.5 KB

__global__ __launch_bounds__(256)
void flash_mma_kernel(const float* __restrict__ mask)
{
    extern __shared__ __align__(16) float sm[];
    float* sQ    = sm;                       // [128][132] tf32
    float* sKV   = sQ  + 128 * QP;           // K stride 132 / V stride 136, tf32
    float* sP    = sKV + 128 * VSTR;         // [128][132] tf32 probs
    float* sRow  = sP  + 128 * PP;           // [128] fp32 row sums
    float* sMask = sRow + 128;               // [2048]

    const int tid  = threadIdx.x;
    const int warp = tid >> 5, lane = tid & 31;
    const int g = lane >> 2, t = lane & 3;
    const int wm = (warp >> 2) * 64, wn = (warp & 3) * 32;

    const int z  = blockIdx.y;
    const int b  = z >> 4;
    const int h  = z & 15;
    const int q0 = blockIdx.x * 128;

    const float* __restrict__ Qg = g_qkv + (size_t)(b * S + q0) * H3 + h * D;

    // load Q (tf32-rounded), mask, zero row sums
#pragma unroll
    for (int i = tid; i < 4096; i += 256) {
        int r = i >> 5, c = (i & 31) * 4;
        float4 v = *reinterpret_cast<const float4*>(Qg + (size_t)r * H3 + c);
        v.x = f2tf(v.x); v.y = f2tf(v.y); v.z = f2tf(v.z); v.w = f2tf(v.w);
        *reinterpret_cast<float4*>(&sQ[r * QP + c]) = v;
    }
#pragma unroll
    for (int i = tid; i < S; i += 256) sMask[i] = mask[(size_t)b * S + i];
    if (tid < 128) sRow[tid] = 0.0f;

    float oacc[4][4][4];
#pragma unroll
    for (int mi = 0; mi < 4; mi++)
#pragma unroll
        for (int nj = 0; nj < 4; nj++)
#pragma unroll
            for (int r = 0; r < 4; r++) oacc[mi][nj][r] = 0.0f;

    for (int jt = 0; jt < S / 128; jt++) {
        const int n0 = jt * 128;
        const float* __restrict__ Kg = g_qkv + (size_t)(b * S + n0) * H3 + H     + h * D;
        const float* __restrict__ Vg = g_qkv + (size_t)(b * S + n0) * H3 + 2 * H + h * D;

        // ---- load K tile [128 keys x 128 d], stride 132, tf32 ----
#pragma unroll
        for (int i = tid; i < 4096; i += 256) {
            int r = i >> 5, c = (i & 31) * 4;
            float4 v = *reinterpret_cast<const float4*>(Kg + (size_t)r * H3 + c);
            v.x = f2tf(v.x); v.y = f2tf(v.y); v.z = f2tf(v.z); v.w = f2tf(v.w);
            *reinterpret_cast<float4*>(&sKV[r * KSTR + c]) = v;
        }
        __syncthreads();                     // Q (iter 0), K, sRow init visible

        // ---- S = Q @ K^T ----
        float sacc[4][4][4];
#pragma unroll
        for (int mi = 0; mi < 4; mi++)
#pragma unroll
            for (int nj = 0; nj < 4; nj++)
#pragma unroll
                for (int r = 0; r < 4; r++) sacc[mi][nj][r] = 0.0f;

#pragma unroll
        for (int kk = 0; kk < D; kk += 8) {
            float af[4][4], bf[4][2];
#pragma unroll
            for (int mi = 0; mi < 4; mi++) {
                const float* base = &sQ[(wm + mi * 16 + g) * QP + kk];
                af[mi][0] = base[t];
                af[mi][1] = base[8 * QP + t];
                af[mi][2] = base[t + 4];
                af[mi][3] = base[8 * QP + t + 4];
            }
#pragma unroll
            for (int nj = 0; nj < 4; nj++) {
                const int key = wn + nj * 8 + g;
                bf[nj][0] = sKV[key * KSTR + kk + t];
                bf[nj][1] = sKV[key * KSTR + kk + t + 4];
            }
#pragma unroll
            for (int mi = 0; mi < 4; mi++)
#pragma unroll
                for (int nj = 0; nj < 4; nj++)
                    mma8(sacc[mi][nj], af[mi], bf[nj]);
        }
        __syncthreads();                     // done reading K; sKV free for V

        // ---- load V tile [128 keys x 128 d], stride 136, tf32 ----
#pragma unroll
        for (int i = tid; i < 4096; i += 256) {
            int r = i >> 5, c = (i & 31) * 4;
            float4 v = *reinterpret_cast<const float4*>(Vg + (size_t)r * H3 + c);
            v.x = f2tf(v.x); v.y = f2tf(v.y); v.z = f2tf(v.z); v.w = f2tf(v.w);
            *reinterpret_cast<float4*>(&sKV[r * VSTR + c]) = v;
        }

        // ---- P = exp(S*scale + mask) in registers; store tf32 P; rowsums ----
#pragma unroll
        for (int mi = 0; mi < 4; mi++) {
            const int r0 = wm + mi * 16 + g;
            float rp0 = 0.0f, rp1 = 0.0f;
#pragma unroll
            for (int nj = 0; nj < 4; nj++) {
                const int col = wn + nj * 8 + 2 * t;
                const float m0v = sMask[n0 + col];
                const float m1v = sMask[n0 + col + 1];
                float p00 = __expf(fmaf(sacc[mi][nj][0], SM_SCALE, m0v));
                float p01 = __expf(fmaf(sacc[mi][nj][1], SM_SCALE, m1v));
                float p10 = __expf(fmaf(sacc[mi][nj][2], SM_SCALE, m0v));
                float p11 = __expf(fmaf(sacc[mi][nj][3], SM_SCALE, m1v));
                rp0 += p00 + p01;
                rp1 += p10 + p11;
                *reinterpret_cast<float2*>(&sP[r0 * PP + col]) =
                    make_float2(f2tf(p00), f2tf(p01));
                *reinterpret_cast<float2*>(&sP[(r0 + 8) * PP + col]) =
                    make_float2(f2tf(p10), f2tf(p11));
            }
            // reduce across the 4 lanes (t) sharing these rows
            rp0 += __shfl_xor_sync(0xffffffffu, rp0, 1);
            rp0 += __shfl_xor_sync(0xffffffffu, rp0, 2);
            rp1 += __shfl_xor_sync(0xffffffffu, rp1, 1);
            rp1 += __shfl_xor_sync(0xffffffffu, rp1, 2);
            if (t == 0) {
                atomicAdd(&sRow[r0], rp0);
                atomicAdd(&sRow[r0 + 8], rp1);
            }
        }
        __syncthreads();                     // P + V visible to all warps

        // ---- O += P @ V ----
#pragma unroll
        for (int kk = 0; kk < 128; kk += 8) {
            float af[4][4], bf[4][2];
#pragma unroll
            for (int mi = 0; mi < 4; mi++) {
                const float* base = &sP[(wm + mi * 16 + g) * PP + kk];
                af[mi][0] = base[t];
                af[mi][1] = base[8 * PP + t];
                af[mi][2] = base[t + 4];
                af[mi][3] = base[8 * PP + t + 4];
            }
#pragma unroll
            for (int nj = 0; nj < 4; nj++) {
                const int col = wn + nj * 8 + g;
                bf[nj][0] = sKV[(kk + t) * VSTR + col];
                bf[nj][1] = sKV[(kk + t + 4) * VSTR + col];
            }
#pragma unroll
            for (int mi = 0; mi < 4; mi++)
#pragma unroll
                for (int nj = 0; nj < 4; nj++)
                    mma8(oacc[mi][nj], af[mi], bf[nj]);
        }
        __syncthreads();                     // before next jt overwrites sKV/sP
    }

    // ---- epilogue: normalize rows, write ctx ----
#pragma unroll
    for (int mi = 0; mi < 4; mi++) {
        const int r0 = wm + mi * 16 + g;
        const float inv0 = 1.0f / sRow[r0];
        const float inv1 = 1.0f / sRow[r0 + 8];
#pragma unroll
        for (int nj = 0; nj < 4; nj++) {
            const int col = wn + nj * 8 + 2 * t;
            float* dst = g_ctx + (size_t)(b * S + q0 + r0) * H + h * D + col;
            *reinterpret_cast<float2*>(dst) =
                make_float2(oacc[mi][nj][0] * inv0, oacc[mi][nj][1] * inv0);
            *reinterpret_cast<float2*>(dst + (size_t)8 * H) =
                make_float2(oacc[mi][nj][2] * inv1, oacc[mi][nj][3] * inv1);
        }
    }
}

// ---------------------------------------------------------------------------
// Launch — inputs identified BY ELEMENT COUNT (robust to ordering).
// ---------------------------------------------------------------------------
extern "C" void kernel_launch(void* const* d_in, const int* in_sizes, int n_in,
                              void* d_out, int out_size)
{
    const float* hidden = nullptr;
    const float* mask   = nullptr;
    const float* W_qkv  = nullptr;
    const float* b_qkv  = nullptr;
    const float* W_out  = nullptr;
    const float* b_out  = nullptr;

    for (int i = 0; i < n_in; i++) {
        switch (in_sizes[i]) {
            case 8388608:  hidden = (const float*)d_in[i]; break;
            case 4096:     mask   = (const float*)d_in[i]; break;
            case 12582912: W_qkv  = (const float*)d_in[i]; break;
            case 6144:     b_qkv  = (const float*)d_in[i]; break;
            case 4194304:  W_out  = (const float*)d_in[i]; break;
            case 2048:     b_out  = (const float*)d_in[i]; break;
            default: break;
        }
    }
    float* out = (float*)d_out;

    cudaFuncSetAttribute(flash_mma_kernel,
                         cudaFuncAttributeMaxDynamicSharedMemorySize,
                         FLASH_SMEM_BYTES);

    float* qkv_ptr;  cudaGetSymbolAddress((void**)&qkv_ptr, g_qkv);
    float* ctx_ptr;  cudaGetSymbolAddress((void**)&ctx_ptr, g_ctx);

    gemm_mma_kernel<<<dim3(H3 / 128, M / 128), 256>>>(
        hidden, H, W_qkv, H3, qkv_ptr, H3, H, b_qkv);

    flash_mma_kernel<<<dim3(S / 128, B * NH), 256, FLASH_SMEM_BYTES>>>(mask);

    gemm_mma_kernel<<<dim3(H / 128, M / 128), 256>>>(
        ctx_ptr, H, W_out, H, out, H, H, b_out);
}

// round 6
// speedup vs baseline: 3.0752x; 1.0079x over previous
#include <cuda_runtime.h>
#include <cstdint>

// ---------------------------------------------------------------------------
// Problem constants
// ---------------------------------------------------------------------------
constexpr int B   = 2;
constexpr int S   = 2048;
constexpr int H   = 2048;
constexpr int NH  = 16;
constexpr int D   = 128;
constexpr int M   = B * S;     // 4096
constexpr int H3  = 3 * H;     // 6144
constexpr float SM_SCALE = 0.08838834764831845f;  // 1/sqrt(128)

// ---------------------------------------------------------------------------
// Scratch
// ---------------------------------------------------------------------------
__device__ float g_qkv[(size_t)M * H3];     // [4096, 6144]
__device__ float g_ctx[(size_t)M * H];      // [4096, 2048]

// ---------------------------------------------------------------------------
// tf32 + mma + cp.async helpers
// ---------------------------------------------------------------------------
__device__ __forceinline__ float f2tf(float x) {
    uint32_t r;
    asm("cvt.rna.tf32.f32 %0, %1;" : "=r"(r) : "f"(x));
    return __uint_as_float(r);
}

// mma.m16n8k8 tf32: D(16x8) = A(16x8) * B(8x8) + C
// A regs: a0=(g,t) a1=(g+8,t) a2=(g,t+4) a3=(g+8,t+4)   [g=lane>>2, t=lane&3]
// B regs: b0=(t,g) b1=(t+4,g)
// C regs: c0=(g,2t) c1=(g,2t+1) c2=(g+8,2t) c3=(g+8,2t+1)
__device__ __forceinline__ void mma8(float* d, const float* a, const float* b) {
    asm volatile(
        "mma.sync.aligned.m16n8k8.row.col.f32.tf32.tf32.f32 "
        "{%0,%1,%2,%3}, {%4,%5,%6,%7}, {%8,%9}, {%0,%1,%2,%3};\n"
        : "+f"(d[0]), "+f"(d[1]), "+f"(d[2]), "+f"(d[3])
        : "r"(__float_as_uint(a[0])), "r"(__float_as_uint(a[1])),
          "r"(__float_as_uint(a[2])), "r"(__float_as_uint(a[3])),
          "r"(__float_as_uint(b[0])), "r"(__float_as_uint(b[1])));
}

__device__ __forceinline__ void cp_async16(void* smem, const void* gmem) {
    uint32_t s = (uint32_t)__cvta_generic_to_shared(smem);
    asm volatile("cp.async.cg.shared.global [%0], [%1], 16;\n"
                 :: "r"(s), "l"(gmem));
}
__device__ __forceinline__ void cp_commit() {
    asm volatile("cp.async.commit_group;\n");
}
template <int N>
__device__ __forceinline__ void cp_wait() {
    asm volatile("cp.async.wait_group %0;\n" :: "n"(N));
}

// ---------------------------------------------------------------------------
// GEMM v2: block 128(m) x 256(n), k-step 32, 8 warps each owning 64x64.
// 2-stage cp.async double buffering; raw fp32 in smem, tf32 cvt at frag load.
//   A stride 36  : frag addr row*36+k  -> bank 4g+t  (conflict-free)
//   B stride 264 : frag addr k*264+col -> bank 8t+g  (conflict-free)
// ---------------------------------------------------------------------------
constexpr int BM = 128, BN = 256, BK = 32;
constexpr int APAD = 36, BPAD = 264;
constexpr int ASZ = BM * APAD;              // 4608 floats
constexpr int BSZ = BK * BPAD;              // 8448 floats
constexpr int GSMEM_BYTES = 2 * (ASZ + BSZ) * 4;   // 104448 B

__global__ __launch_bounds__(256)
void gemm_mma2_kernel(const float* __restrict__ A,  int lda,
                      const float* __restrict__ Bm, int ldb,
                      float* __restrict__ C,        int ldc,
                      int K, const float* __restrict__ bias)
{
    extern __shared__ __align__(16) float sm[];
    float* sA = sm;              // [2][ASZ]
    float* sB = sm + 2 * ASZ;    // [2][BSZ]

    const int tid  = threadIdx.x;
    const int warp = tid >> 5, lane = tid & 31;
    const int g = lane >> 2, t = lane & 3;
    const int wm = (warp >> 2) * 64;        // 0 / 64
    const int wn = (warp & 3) * 64;         // 0 / 64 / 128 / 192
    const int m0 = blockIdx.y * BM, n0 = blockIdx.x * BN;

    A  += (size_t)m0 * lda;
    Bm += n0;
    C  += (size_t)m0 * ldc + n0;

    float acc[4][8][4];
#pragma unroll
    for (int mi = 0; mi < 4; mi++)
#pragma unroll
        for (int nj = 0; nj < 8; nj++)
#pragma unroll
            for (int r = 0; r < 4; r++) acc[mi][nj][r] = 0.0f;

    const int KT = K / BK;

    // ---- async stage loader ----
    auto load_stage = [&](int kt, int buf) {
        const int k0 = kt * BK;
        float* dA = sA + buf * ASZ;
        float* dB = sB + buf * BSZ;
#pragma unroll
        for (int s2 = 0; s2 < 4; s2++) {          // A: 1024 float4
            int idx = tid + s2 * 256;
            int r = idx >> 3, c = (idx & 7) * 4;
            cp_async16(&dA[r * APAD + c], A + (size_t)r * lda + k0 + c);
        }
#pragma unroll
        for (int s2 = 0; s2 < 8; s2++) {          // B: 2048 float4
            int idx = tid + s2 * 256;
            int r = idx >> 6, c = (idx & 63) * 4;
            cp_async16(&dB[r * BPAD + c], Bm + (size_t)(k0 + r) * ldb + c);
        }
        cp_commit();
    };

    load_stage(0, 0);

    for (int kt = 0; kt < KT; kt++) {
        const int buf = kt & 1;
        if (kt + 1 < KT) {
            load_stage(kt + 1, buf ^ 1);
            cp_wait<1>();
        } else {
            cp_wait<0>();
        }
        __syncthreads();

        const float* cA = sA + buf * ASZ;
        const float* cB = sB + buf * BSZ;

#pragma unroll
        for (int kk = 0; kk < BK; kk += 8) {
            float af[4][4], bf[8][2];
#pragma unroll
            for (int mi = 0; mi < 4; mi++) {
                const float* base = &cA[(wm + mi * 16 + g) * APAD + kk];
                af[mi][0] = f2tf(base[t]);
                af[mi][1] = f2tf(base[8 * APAD + t]);
                af[mi][2] = f2tf(base[t + 4]);
                af[mi][3] = f2tf(base[8 * APAD + t + 4]);
            }
#pragma unroll
            for (int nj = 0; nj < 8; nj++) {
                const int col = wn + nj * 8 + g;
                bf[nj][0] = f2tf(cB[(kk + t) * BPAD + col]);
                bf[nj][1] = f2tf(cB[(kk + t + 4) * BPAD + col]);
            }
#pragma unroll
            for (int mi = 0; mi < 4; mi++)
#pragma unroll
                for (int nj = 0; nj < 8; nj++)
                    mma8(acc[mi][nj], af[mi], bf[nj]);
        }
        __syncthreads();
    }

    // ---- epilogue ----
#pragma unroll
    for (int mi = 0; mi < 4; mi++) {
#pragma unroll
        for (int nj = 0; nj < 8; nj++) {
            const int row = wm + mi * 16 + g;
            const int col = wn + nj * 8 + 2 * t;
            const float b0 = bias ? bias[n0 + col]     : 0.0f;
            const float b1 = bias ? bias[n0 + col + 1] : 0.0f;
            float2 lo = make_float2(acc[mi][nj][0] + b0, acc[mi][nj][1] + b1);
            float2 hi = make_float2(acc[mi][nj][2] + b0, acc[mi][nj][3] + b1);
            *reinterpret_cast<float2*>(C + (size_t)row * ldc + col)       = lo;
            *reinterpret_cast<float2*>(C + (size_t)(row + 8) * ldc + col) = hi;
        }
    }
}

// ---------------------------------------------------------------------------
// Fused flash attention with tf32 mma (unchanged from round 5 — passing).
// ---------------------------------------------------------------------------
constexpr int QP = 132, KSTR = 132, VSTR = 136, PP = 132;
constexpr int FLASH_SMEM_FLOATS = 128 * QP + 128 * VSTR + 128 * PP + 128 + S;
constexpr int FLASH_SMEM_BYTES  = FLASH_SMEM_FLOATS * 4;   // ~213.5 KB

__global__ __launch_bounds__(256)
void flash_mma_kernel(const float* __restrict__ mask)
{
    extern __shared__ __align__(16) float sm[];
    float* sQ    = sm;
    float* sKV   = sQ  + 128 * QP;
    float* sP    = sKV + 128 * VSTR;
    float* sRow  = sP  + 128 * PP;
    float* sMask = sRow + 128;

    const int tid  = threadIdx.x;
    const int warp = tid >> 5, lane = tid & 31;
    const int g = lane >> 2, t = lane & 3;
    const int wm = (warp >> 2) * 64, wn = (warp & 3) * 32;

    const int z  = blockIdx.y;
    const int b  = z >> 4;
    const int h  = z & 15;
    const int q0 = blockIdx.x * 128;

    const float* __restrict__ Qg = g_qkv + (size_t)(b * S + q0) * H3 + h * D;

#pragma unroll
    for (int i = tid; i < 4096; i += 256) {
        int r = i >> 5, c = (i & 31) * 4;
        float4 v = *reinterpret_cast<const float4*>(Qg + (size_t)r * H3 + c);
        v.x = f2tf(v.x); v.y = f2tf(v.y); v.z = f2tf(v.z); v.w = f2tf(v.w);
        *reinterpret_cast<float4*>(&sQ[r * QP + c]) = v;
    }
#pragma unroll
    for (int i = tid; i < S; i += 256) sMask[i] = mask[(size_t)b * S + i];
    if (tid < 128) sRow[tid] = 0.0f;

    float oacc[4][4][4];
#pragma unroll
    for (int mi = 0; mi < 4; mi++)
#pragma unroll
        for (int nj = 0; nj < 4; nj++)
#pragma unroll
            for (int r = 0; r < 4; r++) oacc[mi][nj][r] = 0.0f;

    for (int jt = 0; jt < S / 128; jt++) {
        const int n0 = jt * 128;
        const float* __restrict__ Kg = g_qkv + (size_t)(b * S + n0) * H3 + H     + h * D;
        const float* __restrict__ Vg = g_qkv + (size_t)(b * S + n0) * H3 + 2 * H + h * D;

#pragma unroll
        for (int i = tid; i < 4096; i += 256) {
            int r = i >> 5, c = (i & 31) * 4;
            float4 v = *reinterpret_cast<const float4*>(Kg + (size_t)r * H3 + c);
            v.x = f2tf(v.x); v.y = f2tf(v.y); v.z = f2tf(v.z); v.w = f2tf(v.w);
            *reinterpret_cast<float4*>(&sKV[r * KSTR + c]) = v;
        }
        __syncthreads();

        float sacc[4][4][4];
#pragma unroll
        for (int mi = 0; mi < 4; mi++)
#pragma unroll
            for (int nj = 0; nj < 4; nj++)
#pragma unroll
                for (int r = 0; r < 4; r++) sacc[mi][nj][r] = 0.0f;

#pragma unroll
        for (int kk = 0; kk < D; kk += 8) {
            float af[4][4], bf[4][2];
#pragma unroll
            for (int mi = 0; mi < 4; mi++) {
                const float* base = &sQ[(wm + mi * 16 + g) * QP + kk];
                af[mi][0] = base[t];
                af[mi][1] = base[8 * QP + t];
                af[mi][2] = base[t + 4];
                af[mi][3] = base[8 * QP + t + 4];
            }
#pragma unroll
            for (int nj = 0; nj < 4; nj++) {
                const int key = wn + nj * 8 + g;
                bf[nj][0] = sKV[key * KSTR + kk + t];
                bf[nj][1] = sKV[key * KSTR + kk + t + 4];
            }
#pragma unroll
            for (int mi = 0; mi < 4; mi++)
#pragma unroll
                for (int nj = 0; nj < 4; nj++)
                    mma8(sacc[mi][nj], af[mi], bf[nj]);
        }
        __syncthreads();

#pragma unroll
        for (int i = tid; i < 4096; i += 256) {
            int r = i >> 5, c = (i & 31) * 4;
            float4 v = *reinterpret_cast<const float4*>(Vg + (size_t)r * H3 + c);
            v.x = f2tf(v.x); v.y = f2tf(v.y); v.z = f2tf(v.z); v.w = f2tf(v.w);
            *reinterpret_cast<float4*>(&sKV[r * VSTR + c]) = v;
        }

#pragma unroll
        for (int mi = 0; mi < 4; mi++) {
            const int r0 = wm + mi * 16 + g;
            float rp0 = 0.0f, rp1 = 0.0f;
#pragma unroll
            for (int nj = 0; nj < 4; nj++) {
                const int col = wn + nj * 8 + 2 * t;
                const float m0v = sMask[n0 + col];
                const float m1v = sMask[n0 + col + 1];
                float p00 = __expf(fmaf(sacc[mi][nj][0], SM_SCALE, m0v));
                float p01 = __expf(fmaf(sacc[mi][nj][1], SM_SCALE, m1v));
                float p10 = __expf(fmaf(sacc[mi][nj][2], SM_SCALE, m0v));
                float p11 = __expf(fmaf(sacc[mi][nj][3], SM_SCALE, m1v));
                rp0 += p00 + p01;
                rp1 += p10 + p11;
                *reinterpret_cast<float2*>(&sP[r0 * PP + col]) =
                    make_float2(f2tf(p00), f2tf(p01));
                *reinterpret_cast<float2*>(&sP[(r0 + 8) * PP + col]) =
                    make_float2(f2tf(p10), f2tf(p11));
            }
            rp0 += __shfl_xor_sync(0xffffffffu, rp0, 1);
            rp0 += __shfl_xor_sync(0xffffffffu, rp0, 2);
            rp1 += __shfl_xor_sync(0xffffffffu, rp1, 1);
            rp1 += __shfl_xor_sync(0xffffffffu, rp1, 2);
            if (t == 0) {
                atomicAdd(&sRow[r0], rp0);
                atomicAdd(&sRow[r0 + 8], rp1);
            }
        }
        __syncthreads();

#pragma unroll
        for (int kk = 0; kk < 128; kk += 8) {
            float af[4][4], bf[4][2];
#pragma unroll
            for (int mi = 0; mi < 4; mi++) {
                const float* base = &sP[(wm + mi * 16 + g) * PP + kk];
                af[mi][0] = base[t];
                af[mi][1] = base[8 * PP + t];
                af[mi][2] = base[t + 4];
                af[mi][3] = base[8 * PP + t + 4];
            }
#pragma unroll
            for (int nj = 0; nj < 4; nj++) {
                const int col = wn + nj * 8 + g;
                bf[nj][0] = sKV[(kk + t) * VSTR + col];
                bf[nj][1] = sKV[(kk + t + 4) * VSTR + col];
            }
#pragma unroll
            for (int mi = 0; mi < 4; mi++)
#pragma unroll
                for (int nj = 0; nj < 4; nj++)
                    mma8(oacc[mi][nj], af[mi], bf[nj]);
        }
        __syncthreads();
    }

#pragma unroll
    for (int mi = 0; mi < 4; mi++) {
        const int r0 = wm + mi * 16 + g;
        const float inv0 = 1.0f / sRow[r0];
        const float inv1 = 1.0f / sRow[r0 + 8];
#pragma unroll
        for (int nj = 0; nj < 4; nj++) {
            const int col = wn + nj * 8 + 2 * t;
            float* dst = g_ctx + (size_t)(b * S + q0 + r0) * H + h * D + col;
            *reinterpret_cast<float2*>(dst) =
                make_float2(oacc[mi][nj][0] * inv0, oacc[mi][nj][1] * inv0);
            *reinterpret_cast<float2*>(dst + (size_t)8 * H) =
                make_float2(oacc[mi][nj][2] * inv1, oacc[mi][nj][3] * inv1);
        }
    }
}

// ---------------------------------------------------------------------------
// Launch — inputs identified BY ELEMENT COUNT.
// ---------------------------------------------------------------------------
extern "C" void kernel_launch(void* const* d_in, const int* in_sizes, int n_in,
                              void* d_out, int out_size)
{
    const float* hidden = nullptr;
    const float* mask   = nullptr;
    const float* W_qkv  = nullptr;
    const float* b_qkv  = nullptr;
    const float* W_out  = nullptr;
    const float* b_out  = nullptr;

    for (int i = 0; i < n_in; i++) {
        switch (in_sizes[i]) {
            case 8388608:  hidden = (const float*)d_in[i]; break;
            case 4096:     mask   = (const float*)d_in[i]; break;
            case 12582912: W_qkv  = (const float*)d_in[i]; break;
            case 6144:     b_qkv  = (const float*)d_in[i]; break;
            case 4194304:  W_out  = (const float*)d_in[i]; break;
            case 2048:     b_out  = (const float*)d_in[i]; break;
            default: break;
        }
    }
    float* out = (float*)d_out;

    cudaFuncSetAttribute(flash_mma_kernel,
                         cudaFuncAttributeMaxDynamicSharedMemorySize,
                         FLASH_SMEM_BYTES);
    cudaFuncSetAttribute(gemm_mma2_kernel,
                         cudaFuncAttributeMaxDynamicSharedMemorySize,
                         GSMEM_BYTES);

    float* qkv_ptr;  cudaGetSymbolAddress((void**)&qkv_ptr, g_qkv);
    float* ctx_ptr;  cudaGetSymbolAddress((void**)&ctx_ptr, g_ctx);

    gemm_mma2_kernel<<<dim3(H3 / BN, M / BM), 256, GSMEM_BYTES>>>(
        hidden, H, W_qkv, H3, qkv_ptr, H3, H, b_qkv);

    flash_mma_kernel<<<dim3(S / 128, B * NH), 256, FLASH_SMEM_BYTES>>>(mask);

    gemm_mma2_kernel<<<dim3(H / BN, M / BM), 256, GSMEM_BYTES>>>(
        ctx_ptr, H, W_out, H, out, H, H, b_out);
}

// round 8
// speedup vs baseline: 3.4674x; 1.1276x over previous
#include <cuda_runtime.h>
#include <cstdint>

// ---------------------------------------------------------------------------
// Problem constants
// ---------------------------------------------------------------------------
constexpr int B   = 2;
constexpr int S   = 2048;
constexpr int H   = 2048;
constexpr int NH  = 16;
constexpr int D   = 128;
constexpr int M   = B * S;     // 4096
constexpr int H3  = 3 * H;     // 6144
constexpr float SM_SCALE = 0.08838834764831845f;  // 1/sqrt(128)

// ---------------------------------------------------------------------------
// Scratch
// ---------------------------------------------------------------------------
__device__ float g_qkv[(size_t)M * H3];      // [4096, 6144]
__device__ float g_ctx[(size_t)M * H];       // [4096, 2048] (tf32-rounded)
__device__ float g_atf[(size_t)M * H];       // hidden, tf32-rounded
__device__ float g_wqkvt[(size_t)H3 * H];    // W_qkv^T [6144][2048], tf32
__device__ float g_woutt[(size_t)H * H];     // W_out^T [2048][2048], tf32

// ---------------------------------------------------------------------------
// Helpers (all baseline-PTX: sm_75/80 features only — compiles at compute_100)
// ---------------------------------------------------------------------------
__device__ __forceinline__ uint32_t smem_u32(const void* p) {
    uint32_t a;
    asm("{ .reg .u64 t; cvta.to.shared.u64 t, %1; cvt.u32.u64 %0, t; }"
        : "=r"(a) : "l"(p));
    return a;
}
__device__ __forceinline__ float f2tf(float x) {
    uint32_t r;
    asm("cvt.rna.tf32.f32 %0, %1;" : "=r"(r) : "f"(x));
    return __uint_as_float(r);
}
// mma.m16n8k8 tf32 (uint operand form)
__device__ __forceinline__ void mma8u(float* d, const uint32_t* a, const uint32_t* b) {
    asm volatile(
        "mma.sync.aligned.m16n8k8.row.col.f32.tf32.tf32.f32 "
        "{%0,%1,%2,%3}, {%4,%5,%6,%7}, {%8,%9}, {%0,%1,%2,%3};\n"
        : "+f"(d[0]), "+f"(d[1]), "+f"(d[2]), "+f"(d[3])
        : "r"(a[0]), "r"(a[1]), "r"(a[2]), "r"(a[3]), "r"(b[0]), "r"(b[1]));
}
// float operand form (flash kernel)
__device__ __forceinline__ void mma8(float* d, const float* a, const float* b) {
    asm volatile(
        "mma.sync.aligned.m16n8k8.row.col.f32.tf32.tf32.f32 "
        "{%0,%1,%2,%3}, {%4,%5,%6,%7}, {%8,%9}, {%0,%1,%2,%3};\n"
        : "+f"(d[0]), "+f"(d[1]), "+f"(d[2]), "+f"(d[3])
        : "r"(__float_as_uint(a[0])), "r"(__float_as_uint(a[1])),
          "r"(__float_as_uint(a[2])), "r"(__float_as_uint(a[3])),
          "r"(__float_as_uint(b[0])), "r"(__float_as_uint(b[1])));
}
__device__ __forceinline__ void ldm_x4(uint32_t* r, uint32_t addr) {
    asm volatile("ldmatrix.sync.aligned.m8n8.x4.shared.b16 {%0,%1,%2,%3}, [%4];"
                 : "=r"(r[0]), "=r"(r[1]), "=r"(r[2]), "=r"(r[3]) : "r"(addr));
}
__device__ __forceinline__ void cp_async16(void* smem, const void* gmem) {
    uint32_t s = (uint32_t)__cvta_generic_to_shared(smem);
    asm volatile("cp.async.cg.shared.global [%0], [%1], 16;\n" :: "r"(s), "l"(gmem));
}
__device__ __forceinline__ void cp_commit() { asm volatile("cp.async.commit_group;\n"); }
template <int N>
__device__ __forceinline__ void cp_wait() {
    asm volatile("cp.async.wait_group %0;\n" :: "n"(N));
}

// ---------------------------------------------------------------------------
// Prologue 1: elementwise tf32 rounding (hidden -> g_atf)
// ---------------------------------------------------------------------------
__global__ void round_tf32_kernel(const float* __restrict__ in,
                                  float* __restrict__ out, int n4)
{
    int i = blockIdx.x * 256 + threadIdx.x;
    if (i < n4) {
        float4 v = reinterpret_cast<const float4*>(in)[i];
        v.x = f2tf(v.x); v.y = f2tf(v.y); v.z = f2tf(v.z); v.w = f2tf(v.w);
        reinterpret_cast<float4*>(out)[i] = v;
    }
}

// ---------------------------------------------------------------------------
// Prologue 2: W [K][N] -> Wt [N][K], tf32-rounded.  block (32,8), grid (N/32, K/32)
// ---------------------------------------------------------------------------
__global__ void transpose_round_kernel(const float* __restrict__ W,
                                       float* __restrict__ Wt, int K, int N)
{
    __shared__ float t[32][33];
    const int n0 = blockIdx.x * 32, k0 = blockIdx.y * 32;
    const int tx = threadIdx.x, ty = threadIdx.y;
#pragma unroll
    for (int j = 0; j < 4; j++)
        t[ty + 8 * j][tx] = W[(size_t)(k0 + ty + 8 * j) * N + n0 + tx];
    __syncthreads();
#pragma unroll
    for (int j = 0; j < 4; j++)
        Wt[(size_t)(n0 + ty + 8 * j) * K + k0 + tx] = f2tf(t[tx][ty + 8 * j]);
}

// ---------------------------------------------------------------------------
// GEMM: C[128,128/block] = A[M,K] @ Bt[N,K]^T + bias.  A,Bt pre-rounded tf32.
// 128 threads (4 warps, 2x2 of 64x64). cp.async 2-stage; ldmatrix fragments.
// smem stride 36 floats (144B): ldmatrix phases conflict-free (bank 4r+c).
// ---------------------------------------------------------------------------
constexpr int APAD = 36;
constexpr int GA   = 128 * APAD;            // floats per A stage
constexpr int GSTG = 2 * GA;                // A + B per stage
constexpr int GSMEM_BYTES = 2 * GSTG * 4;   // 73728 B

__global__ __launch_bounds__(128)
void gemm_ldm_kernel(const float* __restrict__ A,  int lda,
                     const float* __restrict__ Bt, int ldbt,
                     float* __restrict__ C,        int ldc,
                     int K, const float* __restrict__ bias)
{
    extern __shared__ __align__(16) float sg[];

    const int tid  = threadIdx.x;
    const int warp = tid >> 5, lane = tid & 31;
    const int wm = (warp >> 1) * 64, wn = (warp & 1) * 64;
    const int m0 = blockIdx.y * 128, n0 = blockIdx.x * 128;

    A  += (size_t)m0 * lda;
    Bt += (size_t)n0 * ldbt;
    C  += (size_t)m0 * ldc + n0;

    // ldmatrix per-lane source mapping (A-pattern for both; Bt is [n][k])
    const int rowA = (lane & 7) + (lane & 8);
    const int colA = (lane & 16) ? 4 : 0;
    const int rowB = (lane & 7) + ((lane & 16) >> 1);
    const int colB = (lane & 8) ? 4 : 0;

    float acc[4][8][4];
#pragma unroll
    for (int mi = 0; mi < 4; mi++)
#pragma unroll
        for (int nj = 0; nj < 8; nj++)
#pragma unroll
            for (int r = 0; r < 4; r++) acc[mi][nj][r] = 0.0f;

    auto stage = [&](int kt, int buf) {
        float* dA = sg + buf * GSTG;
        float* dB = dA + GA;
        const int k0 = kt * 32;
#pragma unroll
        for (int j = 0; j < 8; j++) {       // A: 1024 16B chunks / 128 thr
            int idx = tid + j * 128;
            int r = idx >> 3, c = (idx & 7) * 4;
            cp_async16(&dA[r * APAD + c], A + (size_t)r * lda + k0 + c);
        }
#pragma unroll
        for (int j = 0; j < 8; j++) {       // B: rows of Bt (n-major)
            int idx = tid + j * 128;
            int r = idx >> 3, c = (idx & 7) * 4;
            cp_async16(&dB[r * APAD + c], Bt + (size_t)r * ldbt + k0 + c);
        }
        cp_commit();
    };

    stage(0, 0);
    const int KT = K / 32;

    for (int kt = 0; kt < KT; kt++) {
        const int buf = kt & 1;
        if (kt + 1 < KT) { stage(kt + 1, buf ^ 1); cp_wait<1>(); }
        else             { cp_wait<0>(); }
        __syncthreads();

        const float* cA = sg + buf * GSTG;
        const float* cB = cA + GA;
        uint32_t aAdr[4], bAdr[4];
#pragma unroll
        for (int mi = 0; mi < 4; mi++)
            aAdr[mi] = smem_u32(cA + (wm + mi * 16 + rowA) * APAD + colA);
#pragma unroll
        for (int njp = 0; njp < 4; njp++)
            bAdr[njp] = smem_u32(cB + (wn + njp * 16 + rowB) * APAD + colB);

#pragma unroll
        for (int kk = 0; kk < 32; kk += 8) {
            uint32_t a[4][4], bfr[4][4];
#pragma unroll
            for (int mi = 0; mi < 4; mi++)  ldm_x4(a[mi],   aAdr[mi]  + kk * 4);
#pragma unroll
            for (int njp = 0; njp < 4; njp++) ldm_x4(bfr[njp], bAdr[njp] + kk * 4);
#pragma unroll
            for (int mi = 0; mi < 4; mi++)
#pragma unroll
                for (int nj = 0; nj < 8; nj++)
                    mma8u(acc[mi][nj], a[mi], &bfr[nj >> 1][(nj & 1) * 2]);
        }
        __syncthreads();
    }

    // epilogue
#pragma unroll
    for (int mi = 0; mi < 4; mi++) {
#pragma unroll
        for (int nj = 0; nj < 8; nj++) {
            const int g = lane >> 2, t = lane & 3;
            const int row = wm + mi * 16 + g;
            const int col = wn + nj * 8 + 2 * t;
            const float b0 = bias ? bias[n0 + col]     : 0.0f;
            const float b1 = bias ? bias[n0 + col + 1] : 0.0f;
            *reinterpret_cast<float2*>(C + (size_t)row * ldc + col) =
                make_float2(acc[mi][nj][0] + b0, acc[mi][nj][1] + b1);
            *reinterpret_cast<float2*>(C + (size_t)(row + 8) * ldc + col) =
                make_float2(acc[mi][nj][2] + b0, acc[mi][nj][3] + b1);
        }
    }
}

// ---------------------------------------------------------------------------
// Fused flash attention, tf32 mma.sync (round-6 verified; ctx stored tf32)
// ---------------------------------------------------------------------------
constexpr int QP = 132, KSTR = 132, VSTR = 136, PP = 132;
constexpr int FLASH_SMEM_FLOATS = 128 * QP + 128 * VSTR + 128 * PP + 128 + S;
constexpr int FLASH_SMEM_BYTES  = FLASH_SMEM_FLOATS * 4;

__global__ __launch_bounds__(256)
void flash_mma_kernel(const float* __restrict__ mask)
{
    extern __shared__ __align__(16) float sm[];
    float* sQ    = sm;
    float* sKV   = sQ  + 128 * QP;
    float* sP    = sKV + 128 * VSTR;
    float* sRow  = sP  + 128 * PP;
    float* sMask = sRow + 128;

    const int tid  = threadIdx.x;
    const int warp = tid >> 5, lane = tid & 31;
    const int g = lane >> 2, t = lane & 3;
    const int wm = (warp >> 2) * 64, wn = (warp & 3) * 32;

    const int z  = blockIdx.y;
    const int b  = z >> 4;
    const int h  = z & 15;
    const int q0 = blockIdx.x * 128;

    const float* __restrict__ Qg = g_qkv + (size_t)(b * S + q0) * H3 + h * D;

#pragma unroll
    for (int i = tid; i < 4096; i += 256) {
        int r = i >> 5, c = (i & 31) * 4;
        float4 v = *reinterpret_cast<const float4*>(Qg + (size_t)r * H3 + c);
        v.x = f2tf(v.x); v.y = f2tf(v.y); v.z = f2tf(v.z); v.w = f2tf(v.w);
        *reinterpret_cast<float4*>(&sQ[r * QP + c]) = v;
    }
#pragma unroll
    for (int i = tid; i < S; i += 256) sMask[i] = mask[(size_t)b * S + i];
    if (tid < 128) sRow[tid] = 0.0f;

    float oacc[4][4][4];
#pragma unroll
    for (int mi = 0; mi < 4; mi++)
#pragma unroll
        for (int nj = 0; nj < 4; nj++)
#pragma unroll
            for (int r = 0; r < 4; r++) oacc[mi][nj][r] = 0.0f;

    for (int jt = 0; jt < S / 128; jt++) {
        const int n0 = jt * 128;
        const float* __restrict__ Kg = g_qkv + (size_t)(b * S + n0) * H3 + H     + h * D;
        const float* __restrict__ Vg = g_qkv + (size_t)(b * S + n0) * H3 + 2 * H + h * D;

#pragma unroll
        for (int i = tid; i < 4096; i += 256) {
            int r = i >> 5, c = (i & 31) * 4;
            float4 v = *reinterpret_cast<const float4*>(Kg + (size_t)r * H3 + c);
            v.x = f2tf(v.x); v.y = f2tf(v.y); v.z = f2tf(v.z); v.w = f2tf(v.w);
            *reinterpret_cast<float4*>(&sKV[r * KSTR + c]) = v;
        }
        __syncthreads();

        float sacc[4][4][4];
#pragma unroll
        for (int mi = 0; mi < 4; mi++)
#pragma unroll
            for (int nj = 0; nj < 4; nj++)
#pragma unroll
                for (int r = 0; r < 4; r++) sacc[mi][nj][r] = 0.0f;

#pragma unroll
        for (int kk = 0; kk < D; kk += 8) {
            float af[4][4], bf[4][2];
#pragma unroll
            for (int mi = 0; mi < 4; mi++) {
                const float* base = &sQ[(wm + mi * 16 + g) * QP + kk];
                af[mi][0] = base[t];
                af[mi][1] = base[8 * QP + t];
                af[mi][2] = base[t + 4];
                af[mi][3] = base[8 * QP + t + 4];
            }
#pragma unroll
            for (int nj = 0; nj < 4; nj++) {
                const int key = wn + nj * 8 + g;
                bf[nj][0] = sKV[key * KSTR + kk + t];
                bf[nj][1] = sKV[key * KSTR + kk + t + 4];
            }
#pragma unroll
            for (int mi = 0; mi < 4; mi++)
#pragma unroll
                for (int nj = 0; nj < 4; nj++)
                    mma8(sacc[mi][nj], af[mi], bf[nj]);
        }
        __syncthreads();

#pragma unroll
        for (int i = tid; i < 4096; i += 256) {
            int r = i >> 5, c = (i & 31) * 4;
            float4 v = *reinterpret_cast<const float4*>(Vg + (size_t)r * H3 + c);
            v.x = f2tf(v.x); v.y = f2tf(v.y); v.z = f2tf(v.z); v.w = f2tf(v.w);
            *reinterpret_cast<float4*>(&sKV[r * VSTR + c]) = v;
        }

#pragma unroll
        for (int mi = 0; mi < 4; mi++) {
            const int r0 = wm + mi * 16 + g;
            float rp0 = 0.0f, rp1 = 0.0f;
#pragma unroll
            for (int nj = 0; nj < 4; nj++) {
                const int col = wn + nj * 8 + 2 * t;
                const float m0v = sMask[n0 + col];
                const float m1v = sMask[n0 + col + 1];
                float p00 = __expf(fmaf(sacc[mi][nj][0], SM_SCALE, m0v));
                float p01 = __expf(fmaf(sacc[mi][nj][1], SM_SCALE, m1v));
                float p10 = __expf(fmaf(sacc[mi][nj][2], SM_SCALE, m0v));
                float p11 = __expf(fmaf(sacc[mi][nj][3], SM_SCALE, m1v));
                rp0 += p00 + p01;
                rp1 += p10 + p11;
                *reinterpret_cast<float2*>(&sP[r0 * PP + col]) =
                    make_float2(f2tf(p00), f2tf(p01));
                *reinterpret_cast<float2*>(&sP[(r0 + 8) * PP + col]) =
                    make_float2(f2tf(p10), f2tf(p11));
            }
            rp0 += __shfl_xor_sync(0xffffffffu, rp0, 1);
            rp0 += __shfl_xor_sync(0xffffffffu, rp0, 2);
            rp1 += __shfl_xor_sync(0xffffffffu, rp1, 1);
            rp1 += __shfl_xor_sync(0xffffffffu, rp1, 2);
            if (t == 0) {
                atomicAdd(&sRow[r0], rp0);
                atomicAdd(&sRow[r0 + 8], rp1);
            }
        }
        __syncthreads();

#pragma unroll
        for (int kk = 0; kk < 128; kk += 8) {
            float af[4][4], bf[4][2];
#pragma unroll
            for (int mi = 0; mi < 4; mi++) {
                const float* base = &sP[(wm + mi * 16 + g) * PP + kk];
                af[mi][0] = base[t];
                af[mi][1] = base[8 * PP + t];
                af[mi][2] = base[t + 4];
                af[mi][3] = base[8 * PP + t + 4];
            }
#pragma unroll
            for (int nj = 0; nj < 4; nj++) {
                const int col = wn + nj * 8 + g;
                bf[nj][0] = sKV[(kk + t) * VSTR + col];
                bf[nj][1] = sKV[(kk + t + 4) * VSTR + col];
            }
#pragma unroll
            for (int mi = 0; mi < 4; mi++)
#pragma unroll
                for (int nj = 0; nj < 4; nj++)
                    mma8(oacc[mi][nj], af[mi], bf[nj]);
        }
        __syncthreads();
    }

    // ctx stored tf32-rounded (out-proj GEMM consumes pre-rounded A)
#pragma unroll
    for (int mi = 0; mi < 4; mi++) {
        const int r0 = wm + mi * 16 + g;
        const float inv0 = 1.0f / sRow[r0];
        const float inv1 = 1.0f / sRow[r0 + 8];
#pragma unroll
        for (int nj = 0; nj < 4; nj++) {
            const int col = wn + nj * 8 + 2 * t;
            float* dst = g_ctx + (size_t)(b * S + q0 + r0) * H + h * D + col;
            *reinterpret_cast<float2*>(dst) =
                make_float2(f2tf(oacc[mi][nj][0] * inv0), f2tf(oacc[mi][nj][1] * inv0));
            *reinterpret_cast<float2*>(dst + (size_t)8 * H) =
                make_float2(f2tf(oacc[mi][nj][2] * inv1), f2tf(oacc[mi][nj][3] * inv1));
        }
    }
}

// ---------------------------------------------------------------------------
// Launch
// ---------------------------------------------------------------------------
extern "C" void kernel_launch(void* const* d_in, const int* in_sizes, int n_in,
                              void* d_out, int out_size)
{
    const float* hidden = nullptr;
    const float* mask   = nullptr;
    const float* W_qkv  = nullptr;
    const float* b_qkv  = nullptr;
    const float* W_out  = nullptr;
    const float* b_out  = nullptr;

    for (int i = 0; i < n_in; i++) {
        switch (in_sizes[i]) {
            case 8388608:  hidden = (const float*)d_in[i]; break;
            case 4096:     mask   = (const float*)d_in[i]; break;
            case 12582912: W_qkv  = (const float*)d_in[i]; break;
            case 6144:     b_qkv  = (const float*)d_in[i]; break;
            case 4194304:  W_out  = (const float*)d_in[i]; break;
            case 2048:     b_out  = (const float*)d_in[i]; break;
            default: break;
        }
    }
    float* out = (float*)d_out;

    cudaFuncSetAttribute(flash_mma_kernel,
                         cudaFuncAttributeMaxDynamicSharedMemorySize,
                         FLASH_SMEM_BYTES);
    cudaFuncSetAttribute(gemm_ldm_kernel,
                         cudaFuncAttributeMaxDynamicSharedMemorySize,
                         GSMEM_BYTES);

    float* qkv_ptr;   cudaGetSymbolAddress((void**)&qkv_ptr,  g_qkv);
    float* ctx_ptr;   cudaGetSymbolAddress((void**)&ctx_ptr,  g_ctx);
    float* atf_ptr;   cudaGetSymbolAddress((void**)&atf_ptr,  g_atf);
    float* wqkvt_ptr; cudaGetSymbolAddress((void**)&wqkvt_ptr, g_wqkvt);
    float* woutt_ptr; cudaGetSymbolAddress((void**)&woutt_ptr, g_woutt);

    // prologue: pre-round inputs to tf32 (and transpose weights to [n][k])
    round_tf32_kernel<<<(M * H / 4 + 255) / 256, 256>>>(hidden, atf_ptr, M * H / 4);
    transpose_round_kernel<<<dim3(H3 / 32, H / 32), dim3(32, 8)>>>(W_qkv, wqkvt_ptr, H, H3);
    transpose_round_kernel<<<dim3(H / 32, H / 32), dim3(32, 8)>>>(W_out, woutt_ptr, H, H);

    gemm_ldm_kernel<<<dim3(H3 / 128, M / 128), 128, GSMEM_BYTES>>>(
        atf_ptr, H, wqkvt_ptr, H, qkv_ptr, H3, H, b_qkv);

    flash_mma_kernel<<<dim3(S / 128, B * NH), 256, FLASH_SMEM_BYTES>>>(mask);

    gemm_ldm_kernel<<<dim3(H / 128, M / 128), 128, GSMEM_BYTES>>>(
        ctx_ptr, H, woutt_ptr, H, out, H, H, b_out);
}